// round 15
// baseline (speedup 1.0000x reference)
#include <cuda_runtime.h>
#include <math.h>
#include <cstdint>

#define BATCH 16
#define NN    2048
#define KH    12
#define FD    128
#define OD    64

typedef unsigned int uint;

// ---------------- scratch (device globals; no allocation) ----------------
__device__ float g_att[2 * NN * 36];
__device__ int   g_flag[64];

// ---------------------------------------------------------------------------
// Fused kernel: b<4 CTAs each produce 16 of the 64 att jobs for their
// x-range (release-counter); consumers overlap h prefetch with the wait.
// Then R10-verbatim premix + GEMM with smem-staged att.
// ---------------------------------------------------------------------------
#define SM_BHI  0                       // 16384 B
#define SM_BLO  16384
#define SM_AHI  32768                   // 96 rows x 256 B = 24576
#define SM_ALO  57344
#define SM_ATT  81920                   // 2304 floats = 9216 B (waS overlay)
#define SM_TOT  91136

__device__ __forceinline__ void split2(float v0, float v1, uint& hp, uint& lp) {
    asm("cvt.rn.bf16x2.f32 %0, %1, %2;" : "=r"(hp) : "f"(v1), "f"(v0));
    const float h0 = __uint_as_float(hp << 16);
    const float h1 = __uint_as_float(hp & 0xffff0000u);
    asm("cvt.rn.bf16x2.f32 %0, %1, %2;" : "=r"(lp) : "f"(v1 - h1), "f"(v0 - h0));
}
__device__ __forceinline__ uint smem_u32(const void* p) {
    uint a;
    asm("{ .reg .u64 t; cvta.to.shared.u64 t, %1; cvt.u32.u64 %0, t; }"
        : "=r"(a) : "l"(p));
    return a;
}
__device__ __forceinline__ void ldsm4(uint* r, uint addr) {
    asm volatile("ldmatrix.sync.aligned.m8n8.x4.shared.b16 {%0,%1,%2,%3}, [%4];"
                 : "=r"(r[0]), "=r"(r[1]), "=r"(r[2]), "=r"(r[3]) : "r"(addr));
}
__device__ __forceinline__ void mma16816(float* d, const uint* a, uint b0, uint b1) {
    asm volatile("mma.sync.aligned.m16n8k16.row.col.f32.bf16.bf16.f32 "
                 "{%0,%1,%2,%3}, {%4,%5,%6,%7}, {%8,%9}, {%0,%1,%2,%3};"
                 : "+f"(d[0]), "+f"(d[1]), "+f"(d[2]), "+f"(d[3])
                 : "r"(a[0]), "r"(a[1]), "r"(a[2]), "r"(a[3]), "r"(b0), "r"(b1));
}
__device__ __forceinline__ int ld_acquire(const int* p) {
    int v;
    asm volatile("ld.acquire.gpu.s32 %0, [%1];" : "=r"(v) : "l"(p) : "memory");
    return v;
}

__global__ void __launch_bounds__(256, 2) gat_fused_kernel(
    const float* __restrict__ h, const int* __restrict__ adj,
    const float* __restrict__ W, const float* __restrict__ a,
    float* __restrict__ out)
{
    extern __shared__ char smem[];
    const uint sb = smem_u32(smem);
    float* attS = (float*)(smem + SM_ATT);
    float* waS  = (float*)(smem + SM_ATT);      // overlay: dead before attS use
    const int t = threadIdx.x;
    const int w = t >> 5;
    const int lane = t & 31;
    const int b  = blockIdx.y;
    const int nC = blockIdx.x * 32;

    // ---- Bs setup: W -> transposed bf16 hi/lo, XOR-swizzled ----
    {
        uint* BH = (uint*)(smem + SM_BHI);
        uint* BL = (uint*)(smem + SM_BLO);
        #pragma unroll
        for (int j = 0; j < 8; ++j) {
            const int ww = w * 8 + j;
            #pragma unroll
            for (int nh = 0; nh < 2; ++nh) {
                const int n = nh * 32 + lane;
                const float v0 = __ldg(W + (2 * ww) * OD + n);
                const float v1 = __ldg(W + (2 * ww + 1) * OD + n);
                uint hp, lp;
                split2(v0, v1, hp, lp);
                const int word = n * 64 + (ww ^ ((n & 7) << 2));
                BH[word] = hp;
                BL[word] = lp;
            }
        }
    }

    // premix / prefetch geometry (needed in both branches)
    const int nlA = w >> 1;
    const int gl  = w & 1;
    const int tile0 = blockIdx.x * 4;
    float4 hqA[6], hqB[6];
    auto issue_hq = [&](int n0) {
        const float* b1 = h + (((size_t)b * NN + n0 + nlA) * KH + gl * 6) * FD
                            + lane * 4;
        const float* b2 = h + (((size_t)b * NN + n0 + nlA + 4) * KH + gl * 6) * FD
                            + lane * 4;
        #pragma unroll
        for (int q = 0; q < 6; ++q) {
            hqA[q] = *(const float4*)(b1 + q * FD);
            hqB[q] = *(const float4*)(b2 + q * FD);
        }
    };

    // ---- att produce (b<4: one 16-job pass) or prefetch-overlap wait ----
    if (b < 4) {
        {   // wa = W @ a1/a2 for both i
            const int i = t >> 7, f = t & 127;
            float r1 = 0.f, r2 = 0.f;
            const float* wr = W + f * OD;
            const float* ap = a + i * 2 * OD;
            #pragma unroll 16
            for (int o = 0; o < OD; ++o) {
                const float wv = wr[o];
                r1 = fmaf(wv, ap[o], r1);
                r2 = fmaf(wv, ap[OD + o], r2);
            }
            waS[i * 256 + f]       = r1;
            waS[i * 256 + 128 + f] = r2;
        }
        __syncthreads();

        const int hl = lane >> 4;
        const int lf = lane & 15;
        const int job = b * 16 + w * 2 + hl;   // this CTA's 16-job slice
        const int i   = job >> 5;
        const int nl  = job & 31;
        const float* hb = h + (((size_t)i * NN + nC + nl) * KH + i * 6) * FD
                        + 4 * lf;
        const float4 w1a = *(const float4*)(waS + i * 256 + 4 * lf);
        const float4 w1b = *(const float4*)(waS + i * 256 + 64 + 4 * lf);
        const float4 w2a = *(const float4*)(waS + i * 256 + 128 + 4 * lf);
        const float4 w2b = *(const float4*)(waS + i * 256 + 192 + 4 * lf);
        float p1[6], p2[6];
        #pragma unroll
        for (int q = 0; q < 6; ++q) {
            const float4 u = *(const float4*)(hb + q * FD);
            const float4 v = *(const float4*)(hb + q * FD + 64);
            p1[q] = u.x * w1a.x + u.y * w1a.y + u.z * w1a.z + u.w * w1a.w
                  + v.x * w1b.x + v.y * w1b.y + v.z * w1b.z + v.w * w1b.w;
            p2[q] = u.x * w2a.x + u.y * w2a.y + u.z * w2a.z + u.w * w2a.w
                  + v.x * w2b.x + v.y * w2b.y + v.z * w2b.z + v.w * w2b.w;
        }
        #pragma unroll
        for (int off = 8; off > 0; off >>= 1) {
            #pragma unroll
            for (int q = 0; q < 6; ++q) {
                p1[q] += __shfl_xor_sync(0xffffffffu, p1[q], off);
                p2[q] += __shfl_xor_sync(0xffffffffu, p2[q], off);
            }
        }
        if (lf < 6) {
            const int p = lf;
            float e[6];
            float m = -1e30f;
            #pragma unroll
            for (int q = 0; q < 6; ++q) {
                float v = p1[p] + p2[q];
                v = v > 0.f ? v : 0.2f * v;
                if (__ldg(adj + i * 36 + p * 6 + q) <= 0) v = -9.0e15f;
                e[q] = v;
                m = fmaxf(m, v);
            }
            float sum = 0.f;
            #pragma unroll
            for (int q = 0; q < 6; ++q) { e[q] = expf(e[q] - m); sum += e[q]; }
            const float inv = 1.f / sum;
            float* dst = g_att + ((size_t)i * NN + nC + nl) * 36 + p * 6;
            #pragma unroll
            for (int q = 0; q < 6; ++q) dst[q] = e[q] * inv;
        }
        __threadfence();
        __syncthreads();
        if (t == 0) atomicAdd(&g_flag[blockIdx.x], 1);

        issue_hq(tile0 * 8);               // prefetch overlaps own wait
        if (t == 0)
            while (ld_acquire(&g_flag[blockIdx.x]) < 4) __nanosleep(32);
        __syncthreads();
    } else {
        issue_hq(tile0 * 8);               // prefetch overlaps the spin
        if (t == 0)
            while (ld_acquire(&g_flag[blockIdx.x]) < 4) __nanosleep(64);
        __syncthreads();
    }

    // ---- stage att for this x-range into smem (coalesced) ----
    {
        const float4* src = (const float4*)g_att;
        float4* dst = (float4*)attS;
        for (int idx = t; idx < 576; idx += 256) {
            const int gi = idx / 288;
            const int r  = idx - gi * 288;
            dst[gi * 288 + r] = src[((size_t)gi * NN + nC) * 9 + r];
        }
    }
    __syncthreads();

    // ---- R10-verbatim main body (att from smem) ----
    const int wc    = w & 3;
    const int rw    = w >> 2;
    const int g     = lane >> 3;
    const int arow  = ((g & 1) << 3) + (lane & 7);
    const int acoff = g >> 1;
    const int as7   = arow & 7;
    const int nB0   = wc * 16 + (lane >> 2);
    const int nB1   = nB0 + 8;
    const int bxm0  = (nB0 & 7) << 2;
    const int bw0   = lane & 3;
    const uint* BH  = (const uint*)(smem + SM_BHI);
    const uint* BL  = (const uint*)(smem + SM_BLO);
    const int r0l   = lane >> 2;
    const int c0b   = wc * 16 + (lane & 3) * 2;

    // epilogue offsets (tile-invariant)
    int obOff[3][2];
    #pragma unroll
    for (int rti = 0; rti < 3; ++rti)
        #pragma unroll
        for (int hf = 0; hf < 2; ++hf) {
            const int row = (rw * 3 + rti) * 16 + r0l + hf * 8;
            const int nl  = row / 12;
            const int kh  = row - nl * 12;
            obOff[rti][hf] = (nl * KH + kh) * OD + c0b;
        }

    const int cch   = lane >> 1;
    const int half8 = (lane & 1) * 8;
    auto premix_job = [&](const float4* hq, int nloc, int nl) {
        float at[36];
        const float4* ap4 = (const float4*)(attS + (gl * 32 + nloc) * 36);
        #pragma unroll
        for (int k = 0; k < 9; ++k) {
            const float4 v = ap4[k];
            at[k * 4 + 0] = v.x; at[k * 4 + 1] = v.y;
            at[k * 4 + 2] = v.z; at[k * 4 + 3] = v.w;
        }
        const int rbase = nl * 12 + gl * 6;
        #pragma unroll
        for (int p = 0; p < 6; ++p) {
            float a0 = 0.f, a1 = 0.f, a2 = 0.f, a3 = 0.f;
            #pragma unroll
            for (int q = 0; q < 6; ++q) {
                const float aq = at[p * 6 + q];
                a0 = fmaf(aq, hq[q].x, a0);
                a1 = fmaf(aq, hq[q].y, a1);
                a2 = fmaf(aq, hq[q].z, a2);
                a3 = fmaf(aq, hq[q].w, a3);
            }
            uint h0, l0, h1, l1;
            split2(a0, a1, h0, l0);
            split2(a2, a3, h1, l1);
            const int r = rbase + p;
            const uint off = (uint)(r * 256 + ((cch ^ (r & 7)) << 4) + half8);
            *(uint2*)(smem + SM_AHI + off) = make_uint2(h0, h1);
            *(uint2*)(smem + SM_ALO + off) = make_uint2(l0, l1);
        }
    };

    for (int tl = 0; tl < 4; ++tl) {
        const int n0 = (tile0 + tl) * 8;

        premix_job(hqA, tl * 8 + nlA, nlA);
        premix_job(hqB, tl * 8 + nlA + 4, nlA + 4);
        __syncthreads();

        if (tl < 3) issue_hq(n0 + 8);

        float d[3][2][4];
        #pragma unroll
        for (int rti = 0; rti < 3; ++rti)
            #pragma unroll
            for (int ct = 0; ct < 2; ++ct)
                #pragma unroll
                for (int e = 0; e < 4; ++e) d[rti][ct][e] = 0.f;

        #pragma unroll 2
        for (int s = 0; s < 8; ++s) {
            const int i0 = (bw0 + 8 * s) ^ bxm0;
            const int i1 = (bw0 + 4 + 8 * s) ^ bxm0;
            const uint bh0[2] = { BH[nB0 * 64 + i0], BH[nB1 * 64 + i0] };
            const uint bh1[2] = { BH[nB0 * 64 + i1], BH[nB1 * 64 + i1] };
            const uint bl0[2] = { BL[nB0 * 64 + i0], BL[nB1 * 64 + i0] };
            const uint bl1[2] = { BL[nB0 * 64 + i1], BL[nB1 * 64 + i1] };
            #pragma unroll
            for (int rti = 0; rti < 3; ++rti) {
                const int rt = rw * 3 + rti;
                const uint ra = (uint)((rt * 16 + arow) * 256
                                       + (((2 * s + acoff) ^ as7) << 4));
                uint ah[4], al[4];
                ldsm4(ah, sb + SM_AHI + ra);
                ldsm4(al, sb + SM_ALO + ra);
                #pragma unroll
                for (int ct = 0; ct < 2; ++ct) {
                    mma16816(d[rti][ct], ah, bh0[ct], bh1[ct]);
                    mma16816(d[rti][ct], ah, bl0[ct], bl1[ct]);
                    mma16816(d[rti][ct], al, bh0[ct], bh1[ct]);
                }
            }
        }

        float* obase = out + (((size_t)b * NN + n0) * KH) * OD;
        #pragma unroll
        for (int rti = 0; rti < 3; ++rti) {
            #pragma unroll
            for (int hf = 0; hf < 2; ++hf) {
                #pragma unroll
                for (int ct = 0; ct < 2; ++ct) {
                    const float e0r = d[rti][ct][hf * 2];
                    const float e1r = d[rti][ct][hf * 2 + 1];
                    float2 o;
                    o.x = e0r > 0.f ? e0r : expm1f(e0r);
                    o.y = e1r > 0.f ? e1r : expm1f(e1r);
                    *(float2*)(obase + obOff[rti][hf] + ct * 8) = o;
                }
            }
        }
        __syncthreads();
    }
}

// ---------------------------------------------------------------------------
extern "C" void kernel_launch(void* const* d_in, const int* in_sizes, int n_in,
                              void* d_out, int out_size)
{
    (void)in_sizes; (void)n_in; (void)out_size;
    const float* h   = (const float*)d_in[0];
    const int*   adj = (const int*)d_in[1];
    const float* W   = (const float*)d_in[2];
    const float* a   = (const float*)d_in[3];
    float* out = (float*)d_out;

    cudaFuncSetAttribute(gat_fused_kernel,
                         cudaFuncAttributeMaxDynamicSharedMemorySize, SM_TOT);
    gat_fused_kernel<<<dim3(64, BATCH), 256, SM_TOT>>>(h, adj, W, a, out);
}

// round 16
// speedup vs baseline: 1.0446x; 1.0446x over previous
#include <cuda_runtime.h>
#include <math.h>
#include <cstdint>

#define BATCH 16
#define NN    2048
#define KH    12
#define FD    128
#define OD    64

typedef unsigned int uint;

// ---------------- scratch (device globals; no allocation) ----------------
__device__ float g_att[2 * NN * 36];
__device__ int   g_flag[64];

// ---------------------------------------------------------------------------
// Fused kernel: b<2 CTAs each produce 32 of the 64 att jobs for their
// x-range (release-counter); h prefetch overlaps the flag wait.
// Then R10/R14-verbatim premix + GEMM.
// ---------------------------------------------------------------------------
#define SM_BHI  0                       // 16384 B
#define SM_BLO  16384
#define SM_AHI  32768                   // 96 rows x 256 B = 24576
#define SM_ALO  57344
#define SM_WAS  81920                   // 4 x 128 floats = 2048 B
#define SM_TOT  83968

__device__ __forceinline__ void split2(float v0, float v1, uint& hp, uint& lp) {
    asm("cvt.rn.bf16x2.f32 %0, %1, %2;" : "=r"(hp) : "f"(v1), "f"(v0));
    const float h0 = __uint_as_float(hp << 16);
    const float h1 = __uint_as_float(hp & 0xffff0000u);
    asm("cvt.rn.bf16x2.f32 %0, %1, %2;" : "=r"(lp) : "f"(v1 - h1), "f"(v0 - h0));
}
__device__ __forceinline__ uint smem_u32(const void* p) {
    uint a;
    asm("{ .reg .u64 t; cvta.to.shared.u64 t, %1; cvt.u32.u64 %0, t; }"
        : "=r"(a) : "l"(p));
    return a;
}
__device__ __forceinline__ void ldsm4(uint* r, uint addr) {
    asm volatile("ldmatrix.sync.aligned.m8n8.x4.shared.b16 {%0,%1,%2,%3}, [%4];"
                 : "=r"(r[0]), "=r"(r[1]), "=r"(r[2]), "=r"(r[3]) : "r"(addr));
}
__device__ __forceinline__ void mma16816(float* d, const uint* a, uint b0, uint b1) {
    asm volatile("mma.sync.aligned.m16n8k16.row.col.f32.bf16.bf16.f32 "
                 "{%0,%1,%2,%3}, {%4,%5,%6,%7}, {%8,%9}, {%0,%1,%2,%3};"
                 : "+f"(d[0]), "+f"(d[1]), "+f"(d[2]), "+f"(d[3])
                 : "r"(a[0]), "r"(a[1]), "r"(a[2]), "r"(a[3]), "r"(b0), "r"(b1));
}
__device__ __forceinline__ int ld_acquire(const int* p) {
    int v;
    asm volatile("ld.acquire.gpu.s32 %0, [%1];" : "=r"(v) : "l"(p) : "memory");
    return v;
}

__global__ void __launch_bounds__(256, 2) gat_fused_kernel(
    const float* __restrict__ h, const int* __restrict__ adj,
    const float* __restrict__ W, const float* __restrict__ a,
    float* __restrict__ out)
{
    extern __shared__ char smem[];
    const uint sb = smem_u32(smem);
    float* waS = (float*)(smem + SM_WAS);
    const int t = threadIdx.x;
    const int w = t >> 5;
    const int lane = t & 31;
    const int b  = blockIdx.y;
    const int nC = blockIdx.x * 32;

    // ---- Bs setup: W -> transposed bf16 hi/lo, XOR-swizzled ----
    {
        uint* BH = (uint*)(smem + SM_BHI);
        uint* BL = (uint*)(smem + SM_BLO);
        #pragma unroll
        for (int j = 0; j < 8; ++j) {
            const int ww = w * 8 + j;
            #pragma unroll
            for (int nh = 0; nh < 2; ++nh) {
                const int n = nh * 32 + lane;
                const float v0 = __ldg(W + (2 * ww) * OD + n);
                const float v1 = __ldg(W + (2 * ww + 1) * OD + n);
                uint hp, lp;
                split2(v0, v1, hp, lp);
                const int word = n * 64 + (ww ^ ((n & 7) << 2));
                BH[word] = hp;
                BL[word] = lp;
            }
        }
    }

    // prefetch geometry (needed in both branches)
    const int nlA = w >> 1;
    const int gl  = w & 1;
    const int tile0 = blockIdx.x * 4;
    float4 hqA[6], hqB[6];
    auto issue_hq = [&](int n0) {
        const float* b1 = h + (((size_t)b * NN + n0 + nlA) * KH + gl * 6) * FD
                            + lane * 4;
        const float* b2 = h + (((size_t)b * NN + n0 + nlA + 4) * KH + gl * 6) * FD
                            + lane * 4;
        #pragma unroll
        for (int q = 0; q < 6; ++q) {
            hqA[q] = *(const float4*)(b1 + q * FD);
            hqB[q] = *(const float4*)(b2 + q * FD);
        }
    };

    // ---- att produce (b<2: 32 jobs in 2 passes) or overlap-wait ----
    if (b < 2) {
        {   // wa = W @ a1/a2 for both i
            const int i = t >> 7, f = t & 127;
            float r1 = 0.f, r2 = 0.f;
            const float* wr = W + f * OD;
            const float* ap = a + i * 2 * OD;
            #pragma unroll 16
            for (int o = 0; o < OD; ++o) {
                const float wv = wr[o];
                r1 = fmaf(wv, ap[o], r1);
                r2 = fmaf(wv, ap[OD + o], r2);
            }
            waS[i * 256 + f]       = r1;
            waS[i * 256 + 128 + f] = r2;
        }
        __syncthreads();

        const int hl = lane >> 4;
        const int lf = lane & 15;
        #pragma unroll
        for (int pj = 0; pj < 2; ++pj) {
            const int job = b * 32 + pj * 16 + w * 2 + hl;   // 0..63
            const int i   = job >> 5;
            const int nl  = job & 31;
            const float* hb = h + (((size_t)i * NN + nC + nl) * KH + i * 6) * FD
                            + 4 * lf;
            const float4 w1a = *(const float4*)(waS + i * 256 + 4 * lf);
            const float4 w1b = *(const float4*)(waS + i * 256 + 64 + 4 * lf);
            const float4 w2a = *(const float4*)(waS + i * 256 + 128 + 4 * lf);
            const float4 w2b = *(const float4*)(waS + i * 256 + 192 + 4 * lf);
            float p1[6], p2[6];
            #pragma unroll
            for (int q = 0; q < 6; ++q) {
                const float4 u = *(const float4*)(hb + q * FD);
                const float4 v = *(const float4*)(hb + q * FD + 64);
                p1[q] = u.x * w1a.x + u.y * w1a.y + u.z * w1a.z + u.w * w1a.w
                      + v.x * w1b.x + v.y * w1b.y + v.z * w1b.z + v.w * w1b.w;
                p2[q] = u.x * w2a.x + u.y * w2a.y + u.z * w2a.z + u.w * w2a.w
                      + v.x * w2b.x + v.y * w2b.y + v.z * w2b.z + v.w * w2b.w;
            }
            #pragma unroll
            for (int off = 8; off > 0; off >>= 1) {
                #pragma unroll
                for (int q = 0; q < 6; ++q) {
                    p1[q] += __shfl_xor_sync(0xffffffffu, p1[q], off);
                    p2[q] += __shfl_xor_sync(0xffffffffu, p2[q], off);
                }
            }
            if (lf < 6) {
                const int p = lf;
                float e[6];
                float m = -1e30f;
                #pragma unroll
                for (int q = 0; q < 6; ++q) {
                    float v = p1[p] + p2[q];
                    v = v > 0.f ? v : 0.2f * v;
                    if (__ldg(adj + i * 36 + p * 6 + q) <= 0) v = -9.0e15f;
                    e[q] = v;
                    m = fmaxf(m, v);
                }
                float sum = 0.f;
                #pragma unroll
                for (int q = 0; q < 6; ++q) { e[q] = expf(e[q] - m); sum += e[q]; }
                const float inv = 1.f / sum;
                float* dst = g_att + ((size_t)i * NN + nC + nl) * 36 + p * 6;
                #pragma unroll
                for (int q = 0; q < 6; ++q) dst[q] = e[q] * inv;
            }
        }
        __threadfence();
        __syncthreads();
        if (t == 0) atomicAdd(&g_flag[blockIdx.x], 1);

        issue_hq(tile0 * 8);               // prefetch overlaps own wait
        if (t == 0)
            while (ld_acquire(&g_flag[blockIdx.x]) < 2) __nanosleep(32);
        __syncthreads();
    } else {
        issue_hq(tile0 * 8);               // prefetch overlaps the spin
        if (t == 0)
            while (ld_acquire(&g_flag[blockIdx.x]) < 2) __nanosleep(64);
        __syncthreads();
    }

    // ---- R10/R14-verbatim main body ----
    const int wc    = w & 3;
    const int rw    = w >> 2;
    const int g     = lane >> 3;
    const int arow  = ((g & 1) << 3) + (lane & 7);
    const int acoff = g >> 1;
    const int as7   = arow & 7;
    const int nB0   = wc * 16 + (lane >> 2);
    const int nB1   = nB0 + 8;
    const int bxm0  = (nB0 & 7) << 2;
    const int bw0   = lane & 3;
    const uint* BH  = (const uint*)(smem + SM_BHI);
    const uint* BL  = (const uint*)(smem + SM_BLO);
    const int r0l   = lane >> 2;
    const int c0b   = wc * 16 + (lane & 3) * 2;

    const int cch   = lane >> 1;
    const int half8 = (lane & 1) * 8;
    auto premix_job = [&](const float4* hq, int n, int nl) {
        float at[36];
        const float4* ap4 = (const float4*)(g_att + ((size_t)gl * NN + n) * 36);
        #pragma unroll
        for (int k = 0; k < 9; ++k) {
            const float4 v = __ldg(ap4 + k);
            at[k * 4 + 0] = v.x; at[k * 4 + 1] = v.y;
            at[k * 4 + 2] = v.z; at[k * 4 + 3] = v.w;
        }
        const int rbase = nl * 12 + gl * 6;
        #pragma unroll
        for (int p = 0; p < 6; ++p) {
            float a0 = 0.f, a1 = 0.f, a2 = 0.f, a3 = 0.f;
            #pragma unroll
            for (int q = 0; q < 6; ++q) {
                const float aq = at[p * 6 + q];
                a0 = fmaf(aq, hq[q].x, a0);
                a1 = fmaf(aq, hq[q].y, a1);
                a2 = fmaf(aq, hq[q].z, a2);
                a3 = fmaf(aq, hq[q].w, a3);
            }
            uint h0, l0, h1, l1;
            split2(a0, a1, h0, l0);
            split2(a2, a3, h1, l1);
            const int r = rbase + p;
            const uint off = (uint)(r * 256 + ((cch ^ (r & 7)) << 4) + half8);
            *(uint2*)(smem + SM_AHI + off) = make_uint2(h0, h1);
            *(uint2*)(smem + SM_ALO + off) = make_uint2(l0, l1);
        }
    };

    for (int tl = 0; tl < 4; ++tl) {
        const int n0 = (tile0 + tl) * 8;

        premix_job(hqA, n0 + nlA, nlA);
        premix_job(hqB, n0 + nlA + 4, nlA + 4);
        __syncthreads();

        if (tl < 3) issue_hq(n0 + 8);

        float d[3][2][4];
        #pragma unroll
        for (int rti = 0; rti < 3; ++rti)
            #pragma unroll
            for (int ct = 0; ct < 2; ++ct)
                #pragma unroll
                for (int e = 0; e < 4; ++e) d[rti][ct][e] = 0.f;

        #pragma unroll 2
        for (int s = 0; s < 8; ++s) {
            const int i0 = (bw0 + 8 * s) ^ bxm0;
            const int i1 = (bw0 + 4 + 8 * s) ^ bxm0;
            const uint bh0[2] = { BH[nB0 * 64 + i0], BH[nB1 * 64 + i0] };
            const uint bh1[2] = { BH[nB0 * 64 + i1], BH[nB1 * 64 + i1] };
            const uint bl0[2] = { BL[nB0 * 64 + i0], BL[nB1 * 64 + i0] };
            const uint bl1[2] = { BL[nB0 * 64 + i1], BL[nB1 * 64 + i1] };
            #pragma unroll
            for (int rti = 0; rti < 3; ++rti) {
                const int rt = rw * 3 + rti;
                const uint ra = (uint)((rt * 16 + arow) * 256
                                       + (((2 * s + acoff) ^ as7) << 4));
                uint ah[4], al[4];
                ldsm4(ah, sb + SM_AHI + ra);
                ldsm4(al, sb + SM_ALO + ra);
                #pragma unroll
                for (int ct = 0; ct < 2; ++ct) {
                    mma16816(d[rti][ct], ah, bh0[ct], bh1[ct]);
                    mma16816(d[rti][ct], ah, bl0[ct], bl1[ct]);
                    mma16816(d[rti][ct], al, bh0[ct], bh1[ct]);
                }
            }
        }

        #pragma unroll
        for (int rti = 0; rti < 3; ++rti) {
            #pragma unroll
            for (int hf = 0; hf < 2; ++hf) {
                const int row = (rw * 3 + rti) * 16 + r0l + hf * 8;
                const int nl  = row / 12;
                const int kh  = row - nl * 12;
                float* ob = out + (((size_t)b * NN + n0 + nl) * KH + kh) * OD;
                #pragma unroll
                for (int ct = 0; ct < 2; ++ct) {
                    const float e0r = d[rti][ct][hf * 2];
                    const float e1r = d[rti][ct][hf * 2 + 1];
                    float2 o;
                    o.x = e0r > 0.f ? e0r : expm1f(e0r);
                    o.y = e1r > 0.f ? e1r : expm1f(e1r);
                    *(float2*)(ob + c0b + ct * 8) = o;
                }
            }
        }
        __syncthreads();
    }
}

// ---------------------------------------------------------------------------
extern "C" void kernel_launch(void* const* d_in, const int* in_sizes, int n_in,
                              void* d_out, int out_size)
{
    (void)in_sizes; (void)n_in; (void)out_size;
    const float* h   = (const float*)d_in[0];
    const int*   adj = (const int*)d_in[1];
    const float* W   = (const float*)d_in[2];
    const float* a   = (const float*)d_in[3];
    float* out = (float*)d_out;

    cudaFuncSetAttribute(gat_fused_kernel,
                         cudaFuncAttributeMaxDynamicSharedMemorySize, SM_TOT);
    gat_fused_kernel<<<dim3(64, BATCH), 256, SM_TOT>>>(h, adj, W, a, out);
}

// round 17
// speedup vs baseline: 1.2679x; 1.2138x over previous
#include <cuda_runtime.h>
#include <math.h>
#include <cstdint>

#define BATCH 16
#define NN    2048
#define KH    12
#define FD    128
#define OD    64

typedef unsigned int uint;

// ---------------- scratch (device globals; no allocation) ----------------
__device__ float g_att[2 * NN * 36];
__device__ int   g_flag[64];

// ---------------------------------------------------------------------------
// Fused kernel: b==0 CTAs produce attention for their x-range (once);
// h prefetch overlaps the flag wait. Then R10/R14-verbatim premix + GEMM.
// ---------------------------------------------------------------------------
#define SM_BHI  0                       // 16384 B
#define SM_BLO  16384
#define SM_AHI  32768                   // 96 rows x 256 B = 24576
#define SM_ALO  57344
#define SM_WAS  81920                   // 4 x 128 floats = 2048 B
#define SM_TOT  83968

__device__ __forceinline__ void split2(float v0, float v1, uint& hp, uint& lp) {
    asm("cvt.rn.bf16x2.f32 %0, %1, %2;" : "=r"(hp) : "f"(v1), "f"(v0));
    const float h0 = __uint_as_float(hp << 16);
    const float h1 = __uint_as_float(hp & 0xffff0000u);
    asm("cvt.rn.bf16x2.f32 %0, %1, %2;" : "=r"(lp) : "f"(v1 - h1), "f"(v0 - h0));
}
__device__ __forceinline__ uint smem_u32(const void* p) {
    uint a;
    asm("{ .reg .u64 t; cvta.to.shared.u64 t, %1; cvt.u32.u64 %0, t; }"
        : "=r"(a) : "l"(p));
    return a;
}
__device__ __forceinline__ void ldsm4(uint* r, uint addr) {
    asm volatile("ldmatrix.sync.aligned.m8n8.x4.shared.b16 {%0,%1,%2,%3}, [%4];"
                 : "=r"(r[0]), "=r"(r[1]), "=r"(r[2]), "=r"(r[3]) : "r"(addr));
}
__device__ __forceinline__ void mma16816(float* d, const uint* a, uint b0, uint b1) {
    asm volatile("mma.sync.aligned.m16n8k16.row.col.f32.bf16.bf16.f32 "
                 "{%0,%1,%2,%3}, {%4,%5,%6,%7}, {%8,%9}, {%0,%1,%2,%3};"
                 : "+f"(d[0]), "+f"(d[1]), "+f"(d[2]), "+f"(d[3])
                 : "r"(a[0]), "r"(a[1]), "r"(a[2]), "r"(a[3]), "r"(b0), "r"(b1));
}
__device__ __forceinline__ int ld_acquire(const int* p) {
    int v;
    asm volatile("ld.acquire.gpu.s32 %0, [%1];" : "=r"(v) : "l"(p) : "memory");
    return v;
}
__device__ __forceinline__ float elu1(float x) {
    return x > 0.f ? x : (__expf(x) - 1.f);
}

__global__ void __launch_bounds__(256, 2) gat_fused_kernel(
    const float* __restrict__ h, const int* __restrict__ adj,
    const float* __restrict__ W, const float* __restrict__ a,
    float* __restrict__ out)
{
    extern __shared__ char smem[];
    const uint sb = smem_u32(smem);
    float* waS = (float*)(smem + SM_WAS);
    const int t = threadIdx.x;
    const int w = t >> 5;
    const int lane = t & 31;
    const int b  = blockIdx.y;
    const int nC = blockIdx.x * 32;

    // ---- Bs setup: W -> transposed bf16 hi/lo, XOR-swizzled ----
    {
        uint* BH = (uint*)(smem + SM_BHI);
        uint* BL = (uint*)(smem + SM_BLO);
        #pragma unroll
        for (int j = 0; j < 8; ++j) {
            const int ww = w * 8 + j;
            #pragma unroll
            for (int nh = 0; nh < 2; ++nh) {
                const int n = nh * 32 + lane;
                const float v0 = __ldg(W + (2 * ww) * OD + n);
                const float v1 = __ldg(W + (2 * ww + 1) * OD + n);
                uint hp, lp;
                split2(v0, v1, hp, lp);
                const int word = n * 64 + (ww ^ ((n & 7) << 2));
                BH[word] = hp;
                BL[word] = lp;
            }
        }
    }

    // prefetch geometry (needed in both branches)
    const int nlA = w >> 1;
    const int gl  = w & 1;
    const int tile0 = blockIdx.x * 4;
    float4 hqA[6], hqB[6];
    auto issue_hq = [&](int n0) {
        const float* b1 = h + (((size_t)b * NN + n0 + nlA) * KH + gl * 6) * FD
                            + lane * 4;
        const float* b2 = h + (((size_t)b * NN + n0 + nlA + 4) * KH + gl * 6) * FD
                            + lane * 4;
        #pragma unroll
        for (int q = 0; q < 6; ++q) {
            hqA[q] = *(const float4*)(b1 + q * FD);
            hqB[q] = *(const float4*)(b2 + q * FD);
        }
    };

    // ---- att produce (b==0: 64 jobs in 4 passes) or overlap-wait ----
    if (b == 0) {
        {   // wa = W @ a1/a2 for both i
            const int i = t >> 7, f = t & 127;
            float r1 = 0.f, r2 = 0.f;
            const float* wr = W + f * OD;
            const float* ap = a + i * 2 * OD;
            #pragma unroll 16
            for (int o = 0; o < OD; ++o) {
                const float wv = wr[o];
                r1 = fmaf(wv, ap[o], r1);
                r2 = fmaf(wv, ap[OD + o], r2);
            }
            waS[i * 256 + f]       = r1;
            waS[i * 256 + 128 + f] = r2;
        }
        __syncthreads();

        const int hl = lane >> 4;
        const int lf = lane & 15;
        #pragma unroll
        for (int pj = 0; pj < 4; ++pj) {
            const int job = w * 8 + pj * 2 + hl;   // 0..63
            const int i   = job >> 5;
            const int nl  = job & 31;
            const float* hb = h + (((size_t)i * NN + nC + nl) * KH + i * 6) * FD
                            + 4 * lf;
            const float4 w1a = *(const float4*)(waS + i * 256 + 4 * lf);
            const float4 w1b = *(const float4*)(waS + i * 256 + 64 + 4 * lf);
            const float4 w2a = *(const float4*)(waS + i * 256 + 128 + 4 * lf);
            const float4 w2b = *(const float4*)(waS + i * 256 + 192 + 4 * lf);
            float p1[6], p2[6];
            #pragma unroll
            for (int q = 0; q < 6; ++q) {
                const float4 u = *(const float4*)(hb + q * FD);
                const float4 v = *(const float4*)(hb + q * FD + 64);
                p1[q] = u.x * w1a.x + u.y * w1a.y + u.z * w1a.z + u.w * w1a.w
                      + v.x * w1b.x + v.y * w1b.y + v.z * w1b.z + v.w * w1b.w;
                p2[q] = u.x * w2a.x + u.y * w2a.y + u.z * w2a.z + u.w * w2a.w
                      + v.x * w2b.x + v.y * w2b.y + v.z * w2b.z + v.w * w2b.w;
            }
            #pragma unroll
            for (int off = 8; off > 0; off >>= 1) {
                #pragma unroll
                for (int q = 0; q < 6; ++q) {
                    p1[q] += __shfl_xor_sync(0xffffffffu, p1[q], off);
                    p2[q] += __shfl_xor_sync(0xffffffffu, p2[q], off);
                }
            }
            if (lf < 6) {
                const int p = lf;
                float e[6];
                float m = -1e30f;
                #pragma unroll
                for (int q = 0; q < 6; ++q) {
                    float v = p1[p] + p2[q];
                    v = v > 0.f ? v : 0.2f * v;
                    if (__ldg(adj + i * 36 + p * 6 + q) <= 0) v = -9.0e15f;
                    e[q] = v;
                    m = fmaxf(m, v);
                }
                float sum = 0.f;
                #pragma unroll
                for (int q = 0; q < 6; ++q) { e[q] = expf(e[q] - m); sum += e[q]; }
                const float inv = 1.f / sum;
                float* dst = g_att + ((size_t)i * NN + nC + nl) * 36 + p * 6;
                #pragma unroll
                for (int q = 0; q < 6; ++q) dst[q] = e[q] * inv;
            }
        }
        __threadfence();
        __syncthreads();
        if (t == 0) atomicExch(&g_flag[blockIdx.x], 1);
        issue_hq(tile0 * 8);               // prefetch (att already done)
        __syncthreads();
    } else {
        issue_hq(tile0 * 8);               // prefetch overlaps the spin
        if (t == 0)
            while (ld_acquire(&g_flag[blockIdx.x]) == 0) __nanosleep(64);
        __syncthreads();
    }

    // ---- R10/R14-verbatim main body ----
    const int wc    = w & 3;
    const int rw    = w >> 2;
    const int g     = lane >> 3;
    const int arow  = ((g & 1) << 3) + (lane & 7);
    const int acoff = g >> 1;
    const int as7   = arow & 7;
    const int nB0   = wc * 16 + (lane >> 2);
    const int nB1   = nB0 + 8;
    const int bxm0  = (nB0 & 7) << 2;
    const int bw0   = lane & 3;
    const uint* BH  = (const uint*)(smem + SM_BHI);
    const uint* BL  = (const uint*)(smem + SM_BLO);
    const int r0l   = lane >> 2;
    const int c0b   = wc * 16 + (lane & 3) * 2;

    const int cch   = lane >> 1;
    const int half8 = (lane & 1) * 8;
    auto premix_job = [&](const float4* hq, int n, int nl) {
        float at[36];
        const float4* ap4 = (const float4*)(g_att + ((size_t)gl * NN + n) * 36);
        #pragma unroll
        for (int k = 0; k < 9; ++k) {
            const float4 v = __ldg(ap4 + k);
            at[k * 4 + 0] = v.x; at[k * 4 + 1] = v.y;
            at[k * 4 + 2] = v.z; at[k * 4 + 3] = v.w;
        }
        const int rbase = nl * 12 + gl * 6;
        #pragma unroll
        for (int p = 0; p < 6; ++p) {
            float a0 = 0.f, a1 = 0.f, a2 = 0.f, a3 = 0.f;
            #pragma unroll
            for (int q = 0; q < 6; ++q) {
                const float aq = at[p * 6 + q];
                a0 = fmaf(aq, hq[q].x, a0);
                a1 = fmaf(aq, hq[q].y, a1);
                a2 = fmaf(aq, hq[q].z, a2);
                a3 = fmaf(aq, hq[q].w, a3);
            }
            uint h0, l0, h1, l1;
            split2(a0, a1, h0, l0);
            split2(a2, a3, h1, l1);
            const int r = rbase + p;
            const uint off = (uint)(r * 256 + ((cch ^ (r & 7)) << 4) + half8);
            *(uint2*)(smem + SM_AHI + off) = make_uint2(h0, h1);
            *(uint2*)(smem + SM_ALO + off) = make_uint2(l0, l1);
        }
    };

    for (int tl = 0; tl < 4; ++tl) {
        const int n0 = (tile0 + tl) * 8;

        premix_job(hqA, n0 + nlA, nlA);
        premix_job(hqB, n0 + nlA + 4, nlA + 4);
        __syncthreads();

        if (tl < 3) issue_hq(n0 + 8);

        float d[3][2][4];
        #pragma unroll
        for (int rti = 0; rti < 3; ++rti)
            #pragma unroll
            for (int ct = 0; ct < 2; ++ct)
                #pragma unroll
                for (int e = 0; e < 4; ++e) d[rti][ct][e] = 0.f;

        #pragma unroll 2
        for (int s = 0; s < 8; ++s) {
            const int i0 = (bw0 + 8 * s) ^ bxm0;
            const int i1 = (bw0 + 4 + 8 * s) ^ bxm0;
            const uint bh0[2] = { BH[nB0 * 64 + i0], BH[nB1 * 64 + i0] };
            const uint bh1[2] = { BH[nB0 * 64 + i1], BH[nB1 * 64 + i1] };
            const uint bl0[2] = { BL[nB0 * 64 + i0], BL[nB1 * 64 + i0] };
            const uint bl1[2] = { BL[nB0 * 64 + i1], BL[nB1 * 64 + i1] };
            #pragma unroll
            for (int rti = 0; rti < 3; ++rti) {
                const int rt = rw * 3 + rti;
                const uint ra = (uint)((rt * 16 + arow) * 256
                                       + (((2 * s + acoff) ^ as7) << 4));
                uint ah[4], al[4];
                ldsm4(ah, sb + SM_AHI + ra);
                ldsm4(al, sb + SM_ALO + ra);
                #pragma unroll
                for (int ct = 0; ct < 2; ++ct) {
                    mma16816(d[rti][ct], ah, bh0[ct], bh1[ct]);
                    mma16816(d[rti][ct], ah, bl0[ct], bl1[ct]);
                    mma16816(d[rti][ct], al, bh0[ct], bh1[ct]);
                }
            }
        }

        #pragma unroll
        for (int rti = 0; rti < 3; ++rti) {
            #pragma unroll
            for (int hf = 0; hf < 2; ++hf) {
                const int row = (rw * 3 + rti) * 16 + r0l + hf * 8;
                const int nl  = row / 12;
                const int kh  = row - nl * 12;
                float* ob = out + (((size_t)b * NN + n0 + nl) * KH + kh) * OD;
                #pragma unroll
                for (int ct = 0; ct < 2; ++ct) {
                    float2 o;
                    o.x = elu1(d[rti][ct][hf * 2]);
                    o.y = elu1(d[rti][ct][hf * 2 + 1]);
                    *(float2*)(ob + c0b + ct * 8) = o;
                }
            }
        }
        __syncthreads();
    }
}

// ---------------------------------------------------------------------------
extern "C" void kernel_launch(void* const* d_in, const int* in_sizes, int n_in,
                              void* d_out, int out_size)
{
    (void)in_sizes; (void)n_in; (void)out_size;
    const float* h   = (const float*)d_in[0];
    const int*   adj = (const int*)d_in[1];
    const float* W   = (const float*)d_in[2];
    const float* a   = (const float*)d_in[3];
    float* out = (float*)d_out;

    cudaFuncSetAttribute(gat_fused_kernel,
                         cudaFuncAttributeMaxDynamicSharedMemorySize, SM_TOT);
    gat_fused_kernel<<<dim3(64, BATCH), 256, SM_TOT>>>(h, adj, W, a, out);
}